// round 1
// baseline (speedup 1.0000x reference)
#include <cuda_runtime.h>

// ---------------- problem constants ----------------
#define KB     8           // batch
#define KC     64          // channels
#define KHW    76800       // 240*320
#define KCL    10          // clusters
#define ALPHA_C   0.02f
#define DELTA_C   0.5f
#define MINW_C    50.0f

// pass-1 tiling
#define CHUNKS1 30
#define PX1     (KHW / CHUNKS1)   // 2560
#define NBLK1   (KB * CHUNKS1)    // 240

// pass-2 tiling
#define CHUNKS3 75
#define PX3     (KHW / CHUNKS3)   // 1024 = 256 threads * 4 px

// ---------------- device scratch (no allocations allowed) ----------------
__device__ float g_psum[NBLK1][KC][KCL];   // partial sums per block
__device__ float g_pcnt[NBLK1][KCL];       // partial counts per block
__device__ float g_means[KB][KCL][KC];     // normalized means
__device__ float g_d2[KB * KCL];           // sum of intra_d^2 per (b,k)
__device__ float g_nk[KB * KCL];           // indicator counts per (b,k)

// =====================================================================
// K1: per-cluster channel sums + counts.
// Block = (b, pixel-chunk of 2560). 8 warps; each warp owns two 4-channel
// quads. One-hot mask computed once per pixel, reused for 4 channels.
// =====================================================================
__global__ __launch_bounds__(256) void k1_sums(const float* __restrict__ x,
                                               const int* __restrict__ cmask)
{
    __shared__ unsigned char s_cm[PX1];
    __shared__ int s_cnt[KCL];

    const int bid   = blockIdx.x;
    const int b     = bid / CHUNKS1;
    const int chunk = bid % CHUNKS1;
    const int pbase = chunk * PX1;
    const int tid   = threadIdx.x;
    const int lane  = tid & 31;
    const int warp  = tid >> 5;

    if (tid < KCL) s_cnt[tid] = 0;

    // stage masks into smem + per-thread predicated counts
    const int* cmb = cmask + b * KHW + pbase;
    int cnt[KCL];
#pragma unroll
    for (int k = 0; k < KCL; k++) cnt[k] = 0;
    for (int p = tid; p < PX1; p += 256) {
        int v = cmb[p];
        s_cm[p] = (unsigned char)v;
#pragma unroll
        for (int k = 0; k < KCL; k++) cnt[k] += (v == k);
    }
    __syncthreads();

#pragma unroll
    for (int k = 0; k < KCL; k++) {
        int v = cnt[k];
#pragma unroll
        for (int off = 16; off; off >>= 1) v += __shfl_xor_sync(0xffffffffu, v, off);
        if (lane == 0) atomicAdd(&s_cnt[k], v);
    }
    __syncthreads();
    if (tid < KCL) g_pcnt[bid][tid] = (float)s_cnt[tid];

    // main: each warp handles quads {warp, warp+8}
#pragma unroll
    for (int qi = 0; qi < 2; qi++) {
        const int quad = warp + qi * 8;
        const int c0   = quad * 4;
        const float* xp0 = x + ((size_t)(b * KC + c0)) * KHW + pbase;

        float acc[4][KCL];
#pragma unroll
        for (int j = 0; j < 4; j++)
#pragma unroll
            for (int k = 0; k < KCL; k++) acc[j][k] = 0.f;

        for (int p = lane; p < PX1; p += 32) {
            const int cmv = s_cm[p];
            float m[KCL];
#pragma unroll
            for (int k = 0; k < KCL; k++) m[k] = (cmv == k) ? 1.0f : 0.0f;
#pragma unroll
            for (int j = 0; j < 4; j++) {
                const float xv = xp0[j * KHW + p];
#pragma unroll
                for (int k = 0; k < KCL; k++)
                    acc[j][k] = fmaf(m[k], xv, acc[j][k]);
            }
        }

        // warp butterfly reduce, lane 0 stores (no atomics, no pre-zero needed)
#pragma unroll
        for (int j = 0; j < 4; j++) {
#pragma unroll
            for (int k = 0; k < KCL; k++) {
                float v = acc[j][k];
#pragma unroll
                for (int off = 16; off; off >>= 1)
                    v += __shfl_xor_sync(0xffffffffu, v, off);
                if (lane == 0) g_psum[bid][c0 + j][k] = v;
            }
        }
    }
}

// =====================================================================
// K2: reduce partials -> normalized means; zero pass-2 accumulators.
// Grid: 80 blocks (b,k), 64 threads (c).
// =====================================================================
__global__ __launch_bounds__(64) void k2_means()
{
    const int b = blockIdx.x / KCL;
    const int k = blockIdx.x % KCL;
    const int c = threadIdx.x;

    float s = 0.f, cntf = 0.f;
#pragma unroll
    for (int ch = 0; ch < CHUNKS1; ch++) {
        const int bid = b * CHUNKS1 + ch;
        s    += g_psum[bid][c][k];
        cntf += g_pcnt[bid][k];
    }
    const float mean = s / (cntf + 1e-10f);

    float sq = mean * mean;
#pragma unroll
    for (int off = 16; off; off >>= 1) sq += __shfl_xor_sync(0xffffffffu, sq, off);
    __shared__ float s_sq[2];
    if ((c & 31) == 0) s_sq[c >> 5] = sq;
    __syncthreads();
    const float norm = sqrtf(s_sq[0] + s_sq[1]);
    const float inv  = 1.0f / fmaxf(norm, 1e-12f);
    g_means[b][k][c] = mean * inv;

    if (blockIdx.x == 0) {
        for (int i = c; i < KB * KCL; i += 64) { g_d2[i] = 0.f; g_nk[i] = 0.f; }
    }
}

// =====================================================================
// K3: second pass over x. Thread = 4 pixels (float4). Means in padded smem
// (row stride 65 -> conflict-free LDS). Accumulate d^2 and indicator counts
// per (b,k) via shared bins then global atomics.
// =====================================================================
__global__ __launch_bounds__(256) void k3_intra(const float* __restrict__ x,
                                                const int* __restrict__ cmask)
{
    __shared__ float msh[KCL * 65];
    __shared__ float s_d2[KCL];
    __shared__ float s_nk[KCL];

    const int bid   = blockIdx.x;
    const int b     = bid / CHUNKS3;
    const int chunk = bid % CHUNKS3;
    const int pbase = chunk * PX3;
    const int tid   = threadIdx.x;

    for (int i = tid; i < KCL * KC; i += 256) {
        const int k = i / KC, c = i % KC;
        msh[k * 65 + c] = g_means[b][k][c];
    }
    if (tid < KCL) { s_d2[tid] = 0.f; s_nk[tid] = 0.f; }
    __syncthreads();

    const int p0 = pbase + tid * 4;
    const int4 cm4 = *(const int4*)(cmask + b * KHW + p0);
    const float* xb = x + (size_t)b * KC * KHW + p0;

    const float* m0 = &msh[cm4.x * 65];
    const float* m1 = &msh[cm4.y * 65];
    const float* m2 = &msh[cm4.z * 65];
    const float* m3 = &msh[cm4.w * 65];

    float d0 = 0.f, d1 = 0.f, d2v = 0.f, d3 = 0.f;
#pragma unroll
    for (int c = 0; c < KC; c++) {
        const float4 xv = *(const float4*)(xb + (size_t)c * KHW);
        d0 = fmaf(xv.x, m0[c], d0);
        d1 = fmaf(xv.y, m1[c], d1);
        d2v = fmaf(xv.z, m2[c], d2v);
        d3 = fmaf(xv.w, m3[c], d3);
    }

    const float dots[4] = { d0, d1, d2v, d3 };
    const int   kk[4]   = { cm4.x, cm4.y, cm4.z, cm4.w };
#pragma unroll
    for (int i = 0; i < 4; i++) {
        const float dd = 0.5f * (1.0f - dots[i]);
        atomicAdd(&s_d2[kk[i]], dd * dd);
        if (dd > ALPHA_C) atomicAdd(&s_nk[kk[i]], 1.0f);
    }
    __syncthreads();
    if (tid < KCL) {
        atomicAdd(&g_d2[b * KCL + tid], s_d2[tid]);
        atomicAdd(&g_nk[b * KCL + tid], s_nk[tid]);
    }
}

// =====================================================================
// K4: finalize. One block. Inter loss from means (padded smem), intra
// finalize from accumulators, write 3 outputs.
// =====================================================================
__device__ __forceinline__ float block_reduce(float v, float* sred, int tid)
{
#pragma unroll
    for (int off = 16; off; off >>= 1) v += __shfl_xor_sync(0xffffffffu, v, off);
    __syncthreads();                      // protect sred reuse across calls
    if ((tid & 31) == 0) sred[tid >> 5] = v;
    __syncthreads();
    v = (tid < 32) ? sred[tid] : 0.f;
    if (tid < 32) {
#pragma unroll
        for (int off = 16; off; off >>= 1) v += __shfl_xor_sync(0xffffffffu, v, off);
    }
    return v;   // valid on tid 0
}

__global__ __launch_bounds__(1024) void k4_final(float* __restrict__ out)
{
    __shared__ float smeans[KB * KCL * 65];   // padded rows: conflict-free
    __shared__ float sred[32];
    const int tid = threadIdx.x;

    for (int i = tid; i < KB * KCL * KC; i += 1024) {
        const int row = i / KC, c = i % KC;
        smeans[row * 65 + c] = ((const float*)g_means)[i];
    }
    __syncthreads();

    // inter: thread t -> (b,k,l), all 800 off/on-diag slots; skip k==l
    float acc_inter = 0.f;
    if (tid < KB * KCL * KCL) {
        const int b = tid / (KCL * KCL);
        const int r = tid % (KCL * KCL);
        const int k = r / KCL, l = r % KCL;
        if (k != l) {
            const float* mk = &smeans[(b * KCL + k) * 65];
            const float* ml = &smeans[(b * KCL + l) * 65];
            float dot = 0.f;
#pragma unroll
            for (int c = 0; c < KC; c++) dot = fmaf(mk[c], ml[c], dot);
            const float inter_d = 0.5f * (1.0f - dot);
            const float h = fmaxf(DELTA_C - inter_d, 0.0f);
            acc_inter = h * h;
        }
    }

    float acc_intra = 0.f, acc_ind = 0.f;
    if (tid < KB * KCL) {
        const float nk = g_nk[tid];
        const float w  = fmaxf(nk, MINW_C) * (float)KCL;
        acc_intra = g_d2[tid] / w;
        acc_ind   = nk;
    }

    const float tot_inter = block_reduce(acc_inter, sred, tid);
    const float tot_intra = block_reduce(acc_intra, sred, tid);
    const float tot_ind   = block_reduce(acc_ind,   sred, tid);

    if (tid == 0) {
        const float inter_loss = tot_inter / ((float)(KCL * (KCL - 1) / 2) * (float)KB);
        const float intra_loss = (tot_ind > 0.f) ? (tot_intra / (float)KB) : 0.f;
        out[0] = intra_loss + inter_loss;
        out[1] = intra_loss;
        out[2] = inter_loss;
    }
}

// =====================================================================
extern "C" void kernel_launch(void* const* d_in, const int* in_sizes, int n_in,
                              void* d_out, int out_size)
{
    const float* x  = (const float*)d_in[0];
    const int*   cm = (const int*)d_in[1];
    float*       out = (float*)d_out;

    k1_sums<<<NBLK1, 256>>>(x, cm);
    k2_means<<<KB * KCL, 64>>>();
    k3_intra<<<KB * CHUNKS3, 256>>>(x, cm);
    k4_final<<<1, 1024>>>(out);
}

// round 3
// speedup vs baseline: 1.2662x; 1.2662x over previous
#include <cuda_runtime.h>

// ---------------- problem constants ----------------
#define KB     8
#define KC     64
#define KHW    76800      // 240*320
#define KCL    10
#define ALPHA_C   0.02f
#define DELTA_C   0.5f
#define MINW_C    50.0f

// pass-1 tiling: 480 blocks of 1280 pixels
#define CHUNKS1 60
#define PX1     (KHW / CHUNKS1)   // 1280
#define NBLK1   (KB * CHUNKS1)    // 480

// pass-2 tiling: 600 blocks of 1024 pixels (256 thr * 4 px)
#define CHUNKS3 75
#define PX3     (KHW / CHUNKS3)   // 1024
#define NBLK3   (KB * CHUNKS3)    // 600

// ---------------- device scratch (zero-init .bss; each launch restores) ----
__device__ float g_sums[KB][KC][KCL];     // K1 atomically accumulates; K2 zeroes
__device__ float g_cnt[KB][KCL];          // K1 accumulates; K2 zeroes
__device__ float g_means[KB][KCL][KC];    // K2 writes (full overwrite)
__device__ float g_d2[KB * KCL];          // K3 accumulates; finalize zeroes
__device__ float g_nk[KB * KCL];          // K3 accumulates; finalize zeroes
__device__ unsigned int g_tick;           // ticket; finalize zeroes

// ---------------- f32x2 helpers ----------------
__device__ __forceinline__ unsigned long long pack2(float lo, float hi) {
    unsigned long long r;
    asm("mov.b64 %0, {%1, %2};" : "=l"(r) : "f"(lo), "f"(hi));
    return r;
}
__device__ __forceinline__ void unpack2(unsigned long long v, float& lo, float& hi) {
    asm("mov.b64 {%0, %1}, %2;" : "=f"(lo), "=f"(hi) : "l"(v));
}
__device__ __forceinline__ void ffma2(unsigned long long& d,
                                      unsigned long long a, unsigned long long b) {
    asm("fma.rn.f32x2 %0, %1, %2, %0;" : "+l"(d) : "l"(a), "l"(b));
}

// =====================================================================
// K1: per-cluster channel sums + counts.
// 8 warps/block; warp owns an 8-channel slab. One-hot mask packed into
// 5 f32x2 pairs, built ONCE per pixel per warp, reused for 8 channels.
// =====================================================================
__global__ __launch_bounds__(256, 2) void k1_sums(const float* __restrict__ x,
                                                  const int* __restrict__ cmask)
{
    __shared__ unsigned char s_cm[PX1];
    __shared__ int s_cnt[KCL];

    const int bid   = blockIdx.x;
    const int b     = bid / CHUNKS1;
    const int pbase = (bid % CHUNKS1) * PX1;
    const int tid   = threadIdx.x;
    const int lane  = tid & 31;
    const int warp  = tid >> 5;

    if (tid < KCL) s_cnt[tid] = 0;

    // stage masks + per-thread predicated counts
    const int* cmb = cmask + b * KHW + pbase;
    int cnt[KCL];
#pragma unroll
    for (int k = 0; k < KCL; k++) cnt[k] = 0;
#pragma unroll
    for (int i = 0; i < PX1 / 256; i++) {
        const int p = tid + i * 256;
        const int v = cmb[p];
        s_cm[p] = (unsigned char)v;
#pragma unroll
        for (int k = 0; k < KCL; k++) cnt[k] += (v == k);
    }
    __syncthreads();

#pragma unroll
    for (int k = 0; k < KCL; k++) {
        int v = cnt[k];
#pragma unroll
        for (int o = 16; o; o >>= 1) v += __shfl_xor_sync(0xffffffffu, v, o);
        if (lane == 0) atomicAdd(&s_cnt[k], v);
    }
    __syncthreads();
    if (tid < KCL) atomicAdd(&g_cnt[b][tid], (float)s_cnt[tid]);

    // main accumulation
    const int c0 = warp * 8;
    const float* xp = x + ((size_t)(b * KC + c0)) * KHW + pbase;

    unsigned long long acc[8][5];
#pragma unroll
    for (int j = 0; j < 8; j++)
#pragma unroll
        for (int kk = 0; kk < 5; kk++) acc[j][kk] = 0ull;

    for (int p = lane; p < PX1; p += 32) {
        const int cmv = s_cm[p];
        unsigned long long m2[5];
#pragma unroll
        for (int kk = 0; kk < 5; kk++) {
            const float lo = (cmv == 2 * kk)     ? 1.0f : 0.0f;
            const float hi = (cmv == 2 * kk + 1) ? 1.0f : 0.0f;
            m2[kk] = pack2(lo, hi);
        }
#pragma unroll
        for (int j = 0; j < 8; j++) {
            const float xv = xp[(size_t)j * KHW + p];
            const unsigned long long xx = pack2(xv, xv);
#pragma unroll
            for (int kk = 0; kk < 5; kk++) ffma2(acc[j][kk], xx, m2[kk]);
        }
    }

    // warp butterfly reduce, lane0 atomics into global sums
#pragma unroll
    for (int j = 0; j < 8; j++) {
#pragma unroll
        for (int kk = 0; kk < 5; kk++) {
            float lo, hi;
            unpack2(acc[j][kk], lo, hi);
#pragma unroll
            for (int o = 16; o; o >>= 1) {
                lo += __shfl_xor_sync(0xffffffffu, lo, o);
                hi += __shfl_xor_sync(0xffffffffu, hi, o);
            }
            if (lane == 0) {
                atomicAdd(&g_sums[b][c0 + j][2 * kk],     lo);
                atomicAdd(&g_sums[b][c0 + j][2 * kk + 1], hi);
            }
        }
    }
}

// =====================================================================
// K2: normalize means; zero accumulators for next launch.
// =====================================================================
__global__ __launch_bounds__(64) void k2_means()
{
    const int b = blockIdx.x / KCL;
    const int k = blockIdx.x % KCL;
    const int c = threadIdx.x;
    __shared__ float s_sq[2];

    const float cntv = g_cnt[b][k];
    const float sv   = g_sums[b][c][k];
    const float mean = sv / (cntv + 1e-10f);

    float sq = mean * mean;
#pragma unroll
    for (int o = 16; o; o >>= 1) sq += __shfl_xor_sync(0xffffffffu, sq, o);
    if ((c & 31) == 0) s_sq[c >> 5] = sq;
    __syncthreads();

    const float inv = 1.0f / fmaxf(sqrtf(s_sq[0] + s_sq[1]), 1e-12f);
    g_means[b][k][c] = mean * inv;

    // reset (all reads above are before this barrier)
    __syncthreads();
    g_sums[b][c][k] = 0.0f;
    if (c == 0) g_cnt[b][k] = 0.0f;
}

// =====================================================================
// K3: second pass over x (4 px/thread, float4), padded-smem means,
// shared-bin accumulation, global atomics, ticket-last-block finalize.
// =====================================================================
__global__ __launch_bounds__(256) void k3_intra(const float* __restrict__ x,
                                                const int* __restrict__ cmask,
                                                float* __restrict__ out)
{
    __shared__ float msh[KCL * 65];
    __shared__ float s_d2[KCL];
    __shared__ float s_nk[KCL];
    __shared__ unsigned int s_last;

    const int bid   = blockIdx.x;
    const int b     = bid / CHUNKS3;
    const int pbase = (bid % CHUNKS3) * PX3;
    const int tid   = threadIdx.x;
    const int lane  = tid & 31;
    const int warp  = tid >> 5;

    for (int i = tid; i < KCL * KC; i += 256)
        msh[(i >> 6) * 65 + (i & 63)] = ((const float*)g_means)[b * KCL * KC + i];
    if (tid < KCL) { s_d2[tid] = 0.f; s_nk[tid] = 0.f; }
    __syncthreads();

    const int p0 = pbase + tid * 4;
    const int4 cm4 = *(const int4*)(cmask + b * KHW + p0);
    const float* xb = x + (size_t)b * KC * KHW + p0;

    const float* m0  = &msh[cm4.x * 65];
    const float* m1  = &msh[cm4.y * 65];
    const float* m2p = &msh[cm4.z * 65];
    const float* m3  = &msh[cm4.w * 65];

    float d0 = 0.f, d1 = 0.f, d2v = 0.f, d3 = 0.f;
#pragma unroll 16
    for (int c = 0; c < KC; c++) {
        const float4 xv = *(const float4*)(xb + (size_t)c * KHW);
        d0  = fmaf(xv.x, m0[c],  d0);
        d1  = fmaf(xv.y, m1[c],  d1);
        d2v = fmaf(xv.z, m2p[c], d2v);
        d3  = fmaf(xv.w, m3[c],  d3);
    }

    const float dots[4] = { d0, d1, d2v, d3 };
    const int   kk4[4]  = { cm4.x, cm4.y, cm4.z, cm4.w };
#pragma unroll
    for (int i = 0; i < 4; i++) {
        const float dd = 0.5f * (1.0f - dots[i]);
        atomicAdd(&s_d2[kk4[i]], dd * dd);
        if (dd > ALPHA_C) atomicAdd(&s_nk[kk4[i]], 1.0f);
    }
    __syncthreads();
    if (tid < KCL) {
        atomicAdd(&g_d2[b * KCL + tid], s_d2[tid]);
        atomicAdd(&g_nk[b * KCL + tid], s_nk[tid]);
    }

    // ---- ticket: last block finalizes ----
    __threadfence();
    __syncthreads();
    if (tid == 0)
        s_last = (atomicAdd(&g_tick, 1u) == (unsigned)(NBLK3 - 1)) ? 1u : 0u;
    __syncthreads();
    if (!s_last) return;
    __threadfence();

    // ---------- finalize (one block, 256 threads) ----------
    __shared__ float fmsh[KB * KCL * 65];

    for (int i = tid; i < KB * KCL * KC; i += 256)
        fmsh[(i >> 6) * 65 + (i & 63)] = ((const float*)g_means)[i];
    __syncthreads();

    // inter loss: warp-per-ordered-pair (720 pairs / 8 warps).
    // After the butterfly ALL lanes hold d, so only lane 0 accumulates.
    float acc_inter = 0.f;
    for (int pr = warp; pr < KB * KCL * (KCL - 1); pr += 8) {
        const int bb = pr / 90;
        const int r  = pr % 90;
        const int k  = r / 9;
        int l = r % 9; if (l >= k) l++;
        const float* mk = &fmsh[(bb * KCL + k) * 65];
        const float* ml = &fmsh[(bb * KCL + l) * 65];
        float d = mk[lane] * ml[lane] + mk[lane + 32] * ml[lane + 32];
#pragma unroll
        for (int o = 16; o; o >>= 1) d += __shfl_xor_sync(0xffffffffu, d, o);
        const float h = fmaxf(DELTA_C - 0.5f * (1.0f - d), 0.0f);
        if (lane == 0) acc_inter += h * h;          // <-- FIX: lane 0 only
    }

    // intra finalize + resets
    float acc_intra = 0.f, acc_ind = 0.f;
    if (tid < KB * KCL) {
        const float nk = g_nk[tid];
        acc_intra = g_d2[tid] / (fmaxf(nk, MINW_C) * (float)KCL);
        acc_ind   = nk;
        g_nk[tid] = 0.f;
        g_d2[tid] = 0.f;
    }

    // three block reductions
    float v0 = acc_inter, v1 = acc_intra, v2 = acc_ind;
#pragma unroll
    for (int o = 16; o; o >>= 1) {
        v0 += __shfl_xor_sync(0xffffffffu, v0, o);
        v1 += __shfl_xor_sync(0xffffffffu, v1, o);
        v2 += __shfl_xor_sync(0xffffffffu, v2, o);
    }
    __shared__ float s_r0[8], s_r1[8], s_r2[8];
    if (lane == 0) { s_r0[warp] = v0; s_r1[warp] = v1; s_r2[warp] = v2; }
    __syncthreads();
    if (tid == 0) {
        float t0 = 0.f, t1 = 0.f, t2 = 0.f;
#pragma unroll
        for (int w = 0; w < 8; w++) { t0 += s_r0[w]; t1 += s_r1[w]; t2 += s_r2[w]; }
        const float inter_loss = t0 / ((float)(KCL * (KCL - 1) / 2) * (float)KB);
        const float intra_loss = (t2 > 0.f) ? (t1 / (float)KB) : 0.f;
        out[0] = intra_loss + inter_loss;
        out[1] = intra_loss;
        out[2] = inter_loss;
        g_tick = 0u;   // reset ticket for next launch
    }
}

// =====================================================================
extern "C" void kernel_launch(void* const* d_in, const int* in_sizes, int n_in,
                              void* d_out, int out_size)
{
    const float* x   = (const float*)d_in[0];
    const int*   cm  = (const int*)d_in[1];
    float*       out = (float*)d_out;

    k1_sums<<<NBLK1, 256>>>(x, cm);
    k2_means<<<KB * KCL, 64>>>();
    k3_intra<<<NBLK3, 256>>>(x, cm, out);
}